// round 10
// baseline (speedup 1.0000x reference)
#include <cuda_runtime.h>
#include <cuda_bf16.h>
#include <cstdint>
#include <math.h>

#define Bn 4
#define Nn 256
#define Tn 128
#define Fn 64
#define Kn 8
#define Hn 256

// ---------------- scratch (static device globals) ----------------
__device__ float g_ht[Bn*Tn*Nn*Hn];            // h: [b][t][n][h] fp32
__device__ __nv_bfloat16 g_aggbf[Bn*Tn*Nn*Hn]; // lag aggregate bf16: [bt*256+i][h]
__device__ __nv_bfloat16 g_AbfS[Bn*Kn*Nn*Nn];  // alpha-scaled normalized A bf16: [b][k][i][j]
__device__ __nv_bfloat16 g_hbfT[Bn*Tn*Hn*Nn];  // h bf16 transposed: [b][t][h][n]
__device__ __nv_bfloat16 g_owT[Hn*Hn];         // out_w transposed bf16: [o][h]
__device__ float g_part2[64*64];               // ctx partials: [(b*16+chunk)][f]

__device__ __forceinline__ float gelu_f(float v) {
    return 0.5f * v * (1.0f + erff(v * 0.7071067811865476f));
}

__device__ __forceinline__ uint32_t f2tf(float x) {
    uint32_t u;
    asm("cvt.rna.tf32.f32 %0, %1;" : "=r"(u) : "f"(x));
    return u;
}

__device__ __forceinline__ void mma_tf32(float (&d)[4], const uint32_t (&a)[4], const uint32_t (&b)[2]) {
    asm volatile(
        "mma.sync.aligned.m16n8k8.row.col.f32.tf32.tf32.f32 "
        "{%0,%1,%2,%3}, {%4,%5,%6,%7}, {%8,%9}, {%0,%1,%2,%3};"
        : "+f"(d[0]), "+f"(d[1]), "+f"(d[2]), "+f"(d[3])
        : "r"(a[0]), "r"(a[1]), "r"(a[2]), "r"(a[3]), "r"(b[0]), "r"(b[1]));
}

__device__ __forceinline__ void mma_bf16(float (&d)[4], const uint32_t (&a)[4], const uint32_t (&b)[2]) {
    asm volatile(
        "mma.sync.aligned.m16n8k16.row.col.f32.bf16.bf16.f32 "
        "{%0,%1,%2,%3}, {%4,%5,%6,%7}, {%8,%9}, {%0,%1,%2,%3};"
        : "+f"(d[0]), "+f"(d[1]), "+f"(d[2]), "+f"(d[3])
        : "r"(a[0]), "r"(a[1]), "r"(a[2]), "r"(a[3]), "r"(b[0]), "r"(b[1]));
}

__device__ __forceinline__ void ldsm_x4(uint32_t (&r)[4], uint32_t addr) {
    asm volatile("ldmatrix.sync.aligned.m8n8.x4.shared.b16 {%0,%1,%2,%3}, [%4];"
                 : "=r"(r[0]), "=r"(r[1]), "=r"(r[2]), "=r"(r[3]) : "r"(addr));
}

__device__ __forceinline__ uint32_t smem_u32(const void* p) {
    uint32_t a;
    asm("{ .reg .u64 t; cvta.to.shared.u64 t, %1; cvt.u32.u64 %0, t; }" : "=r"(a) : "l"(p));
    return a;
}

__device__ __forceinline__ void cp_async16(uint32_t dst, const void* src) {
    asm volatile("cp.async.cg.shared.global [%0], [%1], 16;" :: "r"(dst), "l"(src));
}

// swizzled byte offset within a [row][32 bf16] tile, rows 64B, 16B-chunk rotation
#define SWC(r, cb) (((r) << 6) + ((((((cb) >> 4) + (((r) >> 1) & 3))) & 3) << 4))

// ---------------- ctx mean partials (grid 64 = b*16 + chunk) ----------------
__global__ __launch_bounds__(256) void k_ctx_a(const float* __restrict__ x) {
    int tid = threadIdx.x;
    int b = blockIdx.x >> 4, ch = blockIdx.x & 15;
    const float* base = x + (size_t)b * 2097152 + (size_t)ch * 131072;  // 2048 rows x 64 f
    int fg = tid & 15, rg = tid >> 4;
    float4 acc = make_float4(0.f, 0.f, 0.f, 0.f);
#pragma unroll 8
    for (int it = 0; it < 128; it++) {
        const float4 v = *(const float4*)(base + (size_t)(it * 16 + rg) * 64 + fg * 4);
        acc.x += v.x; acc.y += v.y; acc.z += v.z; acc.w += v.w;
    }
    __shared__ float4 sm[256];
    sm[tid] = acc;
    __syncthreads();
    if (tid < 16) {
        float4 t = make_float4(0.f, 0.f, 0.f, 0.f);
#pragma unroll
        for (int r2 = 0; r2 < 16; r2++) {
            float4 v = sm[r2 * 16 + tid];
            t.x += v.x; t.y += v.y; t.z += v.z; t.w += v.w;
        }
        *(float4*)&g_part2[blockIdx.x * 64 + tid * 4] = t;
    }
}

// ------ A row-normalize + (redundant per-block) gate MLP + alpha scale + bf16 cast ------
__global__ __launch_bounds__(256) void k_prepA(const float* __restrict__ A_list,
                       const float* __restrict__ lag_embed,
                       const float* __restrict__ cw1, const float* __restrict__ cb1,
                       const float* __restrict__ cw2, const float* __restrict__ cb2,
                       const float* __restrict__ gw1, const float* __restrict__ gb1,
                       const float* __restrict__ gw2, const float* __restrict__ gb2) {
    __shared__ float red[8];
    __shared__ float invs;
    __shared__ float ctx_sm[256];
    __shared__ float alpha_sm[4];
    int row = blockIdx.x;          // row = k*256 + i
    int tid = threadIdx.x;         // j
    float v = A_list[row * 256 + tid];
    float s = v;
#pragma unroll
    for (int o = 16; o > 0; o >>= 1) s += __shfl_xor_sync(0xffffffffu, s, o);
    if ((tid & 31) == 0) red[tid >> 5] = s;
    {   // ctx[b][f] from 16 chunk partials
        int b = tid >> 6, f = tid & 63;
        float cs = 0.f;
#pragma unroll
        for (int c = 0; c < 16; c++) cs += g_part2[(b * 16 + c) * 64 + f];
        ctx_sm[tid] = cs * (1.0f / 32768.0f);
    }
    __syncthreads();
    if (tid == 0) {
        float t = 0.f;
#pragma unroll
        for (int w = 0; w < 8; w++) t += red[w];
        invs = 1.0f / fmaxf(t, 1e-8f);
    }
    if (tid < 4) {                 // gate MLP for b = tid, k = row>>8
        int b = tid, kk = row >> 8;
        float e1[8];
#pragma unroll
        for (int e = 0; e < 8; e++) {
            float t = cb1[e];
            for (int f = 0; f < 64; f++) t += ctx_sm[b * 64 + f] * cw1[f * 8 + e];
            e1[e] = gelu_f(t);
        }
        float cf[8];
#pragma unroll
        for (int e2 = 0; e2 < 8; e2++) {
            float t = cb2[e2];
#pragma unroll
            for (int e = 0; e < 8; e++) t += e1[e] * cw2[e * 8 + e2];
            cf[e2] = t;
        }
        float gg[8];
#pragma unroll
        for (int e = 0; e < 8; e++) {
            float t = gb1[e];
#pragma unroll
            for (int i = 0; i < 16; i++) {
                float gi = (i < 8) ? lag_embed[kk * 8 + i] : cf[i - 8];
                t += gi * gw1[i * 8 + e];
            }
            gg[e] = gelu_f(t);
        }
        float o = gb2[0];
#pragma unroll
        for (int e = 0; e < 8; e++) o += gg[e] * gw2[e];
        alpha_sm[b] = 1.0f / (1.0f + expf(-o));
    }
    __syncthreads();
    float vn = v * invs;
    int k = row >> 8, i = row & 255;
#pragma unroll
    for (int b = 0; b < 4; b++) {
        g_AbfS[((size_t)(b * 8 + k) * 256 + i) * 256 + tid] = __float2bfloat16(alpha_sm[b] * vn);
    }
}

// ---------------- out_w transpose -> bf16 g_owT[o][h] ----------------
__global__ void k_owT(const float* __restrict__ out_w) {
    __shared__ float tile[32][33];
    int h0 = blockIdx.x * 32, o0 = blockIdx.y * 32;
    int tx = threadIdx.x, ty = threadIdx.y;
#pragma unroll
    for (int p = 0; p < 4; p++)
        tile[ty + p * 8][tx] = out_w[(h0 + ty + p * 8) * 256 + o0 + tx];
    __syncthreads();
#pragma unroll
    for (int p = 0; p < 4; p++)
        g_owT[(size_t)(o0 + ty + p * 8) * 256 + h0 + tx] = __float2bfloat16(tile[tx][ty + p * 8]);
}

// ---------------- K1: h = x@in_w + in_b (tf32 mma), write g_ht fp32 + g_hbfT bf16^T
union SmemH {
    struct { uint32_t As[32 * 132]; uint32_t Bs[32 * 132]; } g;
    __nv_bfloat16 tr[128 * 136];
};

__global__ __launch_bounds__(256) void k_h2(const float* __restrict__ x,
                                            const float* __restrict__ in_w,
                                            const float* __restrict__ in_b) {
    __shared__ SmemH sm;
    int tid = threadIdx.x, lane = tid & 31, warp = tid >> 5;
    int n0 = blockIdx.x * 128, h0 = blockIdx.y * 128;
    int bt = blockIdx.z, b = bt >> 7, t = bt & 127;
    int wm = warp & 1, wn = warp >> 1;     // warp tile 64(n-rows) x 32(h-cols)
    int r = lane >> 2, cl = lane & 3;

    float acc[4][4][4];
#pragma unroll
    for (int mt = 0; mt < 4; mt++)
#pragma unroll
        for (int nt = 0; nt < 4; nt++)
#pragma unroll
            for (int e = 0; e < 4; e++) acc[mt][nt][e] = 0.f;

    for (int f0 = 0; f0 < 64; f0 += 32) {
        __syncthreads();
        {   // x tile -> As[f][n] (tf32)
            int f = tid & 31, nb = tid >> 5;
            const float* xb = x + (((size_t)(b * 256 + n0) * 128 + t) * 64) + f0 + f;
#pragma unroll
            for (int p = 0; p < 16; p++) {
                int nn = nb + p * 8;
                sm.g.As[f * 132 + nn] = f2tf(xb[(size_t)nn * 8192]);
            }
        }
        {   // w tile -> Bs[f][h] (tf32)
#pragma unroll
            for (int p = 0; p < 16; p++) {
                int idx = tid + p * 256;
                int f = idx >> 7, c = idx & 127;
                sm.g.Bs[f * 132 + c] = f2tf(in_w[(f0 + f) * 256 + h0 + c]);
            }
        }
        __syncthreads();
#pragma unroll
        for (int ks = 0; ks < 4; ks++) {
            int ko = ks * 8;
            uint32_t a[4][4], bfr[4][2];
#pragma unroll
            for (int mt = 0; mt < 4; mt++) {
                int rb = wm * 64 + mt * 16 + r;
                a[mt][0] = sm.g.As[(ko + cl) * 132 + rb];
                a[mt][1] = sm.g.As[(ko + cl) * 132 + rb + 8];
                a[mt][2] = sm.g.As[(ko + 4 + cl) * 132 + rb];
                a[mt][3] = sm.g.As[(ko + 4 + cl) * 132 + rb + 8];
            }
#pragma unroll
            for (int nt = 0; nt < 4; nt++) {
                int nb2 = wn * 32 + nt * 8 + r;
                bfr[nt][0] = sm.g.Bs[(ko + cl) * 132 + nb2];
                bfr[nt][1] = sm.g.Bs[(ko + 4 + cl) * 132 + nb2];
            }
#pragma unroll
            for (int mt = 0; mt < 4; mt++)
#pragma unroll
                for (int nt = 0; nt < 4; nt++)
                    mma_tf32(acc[mt][nt], a[mt], bfr[nt]);
        }
    }

    // add bias, write fp32 g_ht (coalesced)
    float* Og = g_ht + (size_t)bt * 65536;
#pragma unroll
    for (int mt = 0; mt < 4; mt++) {
        int row = wm * 64 + mt * 16 + r;
#pragma unroll
        for (int nt = 0; nt < 4; nt++) {
            int col = wn * 32 + nt * 8 + 2 * cl;
            float2 ob = *(const float2*)&in_b[h0 + col];
            acc[mt][nt][0] += ob.x;  acc[mt][nt][1] += ob.y;
            acc[mt][nt][2] += ob.x;  acc[mt][nt][3] += ob.y;
            *(float2*)(Og + (size_t)(n0 + row) * 256 + h0 + col)     = make_float2(acc[mt][nt][0], acc[mt][nt][1]);
            *(float2*)(Og + (size_t)(n0 + row + 8) * 256 + h0 + col) = make_float2(acc[mt][nt][2], acc[mt][nt][3]);
        }
    }

    // stage bf16 transpose in smem: tr[h][n]
    __syncthreads();
#pragma unroll
    for (int mt = 0; mt < 4; mt++) {
        int row = wm * 64 + mt * 16 + r;
#pragma unroll
        for (int nt = 0; nt < 4; nt++) {
            int col = wn * 32 + nt * 8 + 2 * cl;
            sm.tr[(col)     * 136 + row]     = __float2bfloat16(acc[mt][nt][0]);
            sm.tr[(col + 1) * 136 + row]     = __float2bfloat16(acc[mt][nt][1]);
            sm.tr[(col)     * 136 + row + 8] = __float2bfloat16(acc[mt][nt][2]);
            sm.tr[(col + 1) * 136 + row + 8] = __float2bfloat16(acc[mt][nt][3]);
        }
    }
    __syncthreads();
    __nv_bfloat16* Dst = g_hbfT + (size_t)bt * 65536;
#pragma unroll
    for (int p = 0; p < 32; p++) {
        int idx = tid + p * 256;
        int h = idx >> 6, np = idx & 63;
        uint32_t v = *(uint32_t*)&sm.tr[h * 136 + np * 2];
        *(uint32_t*)(Dst + (size_t)(h0 + h) * 256 + n0 + np * 2) = v;
    }
}

// ---------------- K2: bf16 mma GEMM, 128i x 256h CTA, 512 threads, 3-stage dynamic smem
// Per stage: A (128 x 32 bf16 = 8KB) at +0, B (256 x 32 bf16 = 16KB) at +8192. Stage stride 24576.
#define SP_STAGE 24576
#define SP_SMEM  (3 * SP_STAGE)   // 73728 bytes dynamic

__global__ __launch_bounds__(512, 1) void k_spatial_bf16() {
    extern __shared__ __align__(16) char smem[];
    int tid = threadIdx.x, lane = tid & 31, warp = tid >> 5;
    int i0 = blockIdx.x * 128;
    int bt = blockIdx.y, b = bt >> 7, t = bt & 127;
    int wm = warp & 1, wn = warp >> 1;    // 16 warps: 2(m) x 8(n); warp tile 64 x 32

    float acc[4][4][4];
#pragma unroll
    for (int mt = 0; mt < 4; mt++)
#pragma unroll
        for (int nt = 0; nt < 4; nt++)
#pragma unroll
            for (int e = 0; e < 4; e++) acc[mt][nt][e] = 0.f;

    int nlag = (t + 1 < 8) ? (t + 1) : 8;
    int nch = nlag * 8;

    const char* Ab = (const char*)g_AbfS + (size_t)b * 8 * 131072 + (size_t)i0 * 512;
    const char* Hb = (const char*)g_hbfT + (size_t)(b * 128 + t) * 131072;

    uint32_t sbase = smem_u32(smem);

    int lrow = tid >> 2, lcb = (tid & 3) * 16;   // lrow 0..127
    int lswz = SWC(lrow, lcb);
    int gbyte0 = lrow * 512 + lcb;

    auto issue = [&](int c, int s) {
        int lag = c >> 3, j0b = (c & 7) * 64;
        const char* asrc = Ab + (size_t)lag * 131072 + j0b;
        const char* bsrc = Hb - (size_t)lag * 131072 + j0b;
        uint32_t sa = sbase + s * SP_STAGE;
        uint32_t sbuf = sa + 8192;
        cp_async16(sa + lswz, asrc + gbyte0);                                   // A rows 0..127
        cp_async16(sbuf + lswz, bsrc + gbyte0);                                 // B rows 0..127
        cp_async16(sbuf + SWC(lrow + 128, lcb), bsrc + gbyte0 + 65536);         // B rows 128..255
        asm volatile("cp.async.commit_group;" ::: "memory");
    };

    issue(0, 0);
    issue(1, 1);

    int arow = wm * 64 + (lane & 15);
    int akb = (lane >> 4) * 16;
    int brow = wn * 32 + (lane & 7) + (lane >> 4) * 8;
    int bkb = ((lane >> 3) & 1) * 16;

    int s = 0, sIss = 2;
    for (int c = 0; c < nch; ++c) {
        if (c == nch - 1) asm volatile("cp.async.wait_group 0;" ::: "memory");
        else              asm volatile("cp.async.wait_group 1;" ::: "memory");
        __syncthreads();
        if (c + 2 < nch) issue(c + 2, sIss);
        uint32_t sa = sbase + s * SP_STAGE;
        uint32_t sbuf = sa + 8192;
#pragma unroll
        for (int ks = 0; ks < 2; ks++) {
            uint32_t a[4][4];
#pragma unroll
            for (int mt = 0; mt < 4; mt++)
                ldsm_x4(a[mt], sa + SWC(arow + mt * 16, ks * 32 + akb));
            uint32_t bb[2][4];
#pragma unroll
            for (int np = 0; np < 2; np++)
                ldsm_x4(bb[np], sbuf + SWC(brow + np * 16, ks * 32 + bkb));
#pragma unroll
            for (int mt = 0; mt < 4; mt++)
#pragma unroll
                for (int nt = 0; nt < 4; nt++) {
                    uint32_t bfr[2] = { bb[nt >> 1][(nt & 1) * 2], bb[nt >> 1][(nt & 1) * 2 + 1] };
                    mma_bf16(acc[mt][nt], a[mt], bfr);
                }
        }
        if (++s == 3) s = 0;
        if (++sIss == 3) sIss = 0;
    }

    int r = lane >> 2, cl = lane & 3;
    __nv_bfloat16* Og = g_aggbf + (size_t)bt * 65536;
#pragma unroll
    for (int mt = 0; mt < 4; mt++) {
        int row = i0 + wm * 64 + mt * 16 + r;
#pragma unroll
        for (int nt = 0; nt < 4; nt++) {
            int col = wn * 32 + nt * 8 + 2 * cl;
            __nv_bfloat162 v0 = make_bfloat162(__float2bfloat16(acc[mt][nt][0]), __float2bfloat16(acc[mt][nt][1]));
            __nv_bfloat162 v1 = make_bfloat162(__float2bfloat16(acc[mt][nt][2]), __float2bfloat16(acc[mt][nt][3]));
            *(__nv_bfloat162*)(Og + (size_t)row * 256 + col)       = v0;
            *(__nv_bfloat162*)(Og + (size_t)(row + 8) * 256 + col) = v1;
        }
    }
}

// ---------------- K3: out2 = agg@out_w (bf16 mma); +out_b +h; LN; GELU; transpose
__global__ __launch_bounds__(256) void k_out_bf16(const float* __restrict__ out_b,
                                                  const float* __restrict__ ln_g,
                                                  const float* __restrict__ ln_b,
                                                  float* __restrict__ out) {
    __shared__ __align__(16) char sA[2][4096];    // 64 rows x 64B
    __shared__ __align__(16) char sB[2][16384];   // 256 rows(o) x 64B
    __shared__ float red[64 * 16];                // [row][warp][s,s2]
    int tid = threadIdx.x, lane = tid & 31, warp = tid >> 5;
    int r0 = blockIdx.x * 64;                     // rows = bt*256 + n
    int r = lane >> 2, cl = lane & 3;

    float acc[4][4][4];
#pragma unroll
    for (int mt = 0; mt < 4; mt++)
#pragma unroll
        for (int nt = 0; nt < 4; nt++)
#pragma unroll
            for (int e = 0; e < 4; e++) acc[mt][nt][e] = 0.f;

    uint32_t sAb[2] = { smem_u32(sA[0]), smem_u32(sA[1]) };
    uint32_t sBb[2] = { smem_u32(sB[0]), smem_u32(sB[1]) };

    const char* Abase = (const char*)g_aggbf + (size_t)r0 * 512;
    const char* Bbase = (const char*)g_owT;

    int lrow = tid >> 2, lcb = (tid & 3) * 16;
    int lswz = SWC(lrow, lcb);

    auto issue = [&](int c, int s) {
        int j0b = c * 64;
        cp_async16(sAb[s] + lswz, Abase + (size_t)lrow * 512 + j0b + lcb);
#pragma unroll
        for (int p = 0; p < 4; p++) {
            int row = lrow + p * 64;
            cp_async16(sBb[s] + SWC(row, lcb), Bbase + (size_t)row * 512 + j0b + lcb);
        }
        asm volatile("cp.async.commit_group;" ::: "memory");
    };

    issue(0, 0);
    issue(1, 1);

    int arow = lane & 15;
    int akb = (lane >> 4) * 16;
    int brow = warp * 32 + (lane & 7) + (lane >> 4) * 8;
    int bkb = ((lane >> 3) & 1) * 16;

    for (int c = 0; c < 8; ++c) {
        int s = c & 1;
        if (c == 7) asm volatile("cp.async.wait_group 0;" ::: "memory");
        else        asm volatile("cp.async.wait_group 1;" ::: "memory");
        __syncthreads();
#pragma unroll
        for (int ks = 0; ks < 2; ks++) {
            uint32_t a[4][4];
#pragma unroll
            for (int mt = 0; mt < 4; mt++)
                ldsm_x4(a[mt], sAb[s] + SWC(arow + mt * 16, ks * 32 + akb));
            uint32_t bb[2][4];
#pragma unroll
            for (int np = 0; np < 2; np++)
                ldsm_x4(bb[np], sBb[s] + SWC(brow + np * 16, ks * 32 + bkb));
#pragma unroll
            for (int mt = 0; mt < 4; mt++)
#pragma unroll
                for (int nt = 0; nt < 4; nt++) {
                    uint32_t bfr[2] = { bb[nt >> 1][(nt & 1) * 2], bb[nt >> 1][(nt & 1) * 2 + 1] };
                    mma_bf16(acc[mt][nt], a[mt], bfr);
                }
        }
        __syncthreads();
        if (c + 2 < 8) issue(c + 2, s);
    }

    // epilogue: residual + LN stats.  rows: mt*16 + rr*8 + r ; cols: warp*32 + nt*8 + 2cl
#pragma unroll
    for (int mt = 0; mt < 4; mt++) {
#pragma unroll
        for (int rr = 0; rr < 2; rr++) {
            int row_local = mt * 16 + rr * 8 + r;
            size_t rg = (size_t)r0 + row_local;
            const float* hrow = g_ht + rg * 256;
            float ss = 0.f, ss2 = 0.f;
#pragma unroll
            for (int nt = 0; nt < 4; nt++) {
                int col = warp * 32 + nt * 8 + 2 * cl;
                float2 hb = *(const float2*)&hrow[col];
                float2 ob = *(const float2*)&out_b[col];
                float v0 = acc[mt][nt][rr * 2 + 0] + ob.x + hb.x;
                float v1 = acc[mt][nt][rr * 2 + 1] + ob.y + hb.y;
                acc[mt][nt][rr * 2 + 0] = v0;
                acc[mt][nt][rr * 2 + 1] = v1;
                ss += v0 + v1;
                ss2 += v0 * v0 + v1 * v1;
            }
            ss += __shfl_xor_sync(0xffffffffu, ss, 1);
            ss2 += __shfl_xor_sync(0xffffffffu, ss2, 1);
            ss += __shfl_xor_sync(0xffffffffu, ss, 2);
            ss2 += __shfl_xor_sync(0xffffffffu, ss2, 2);
            if (cl == 0) {
                red[row_local * 16 + warp * 2 + 0] = ss;
                red[row_local * 16 + warp * 2 + 1] = ss2;
            }
        }
    }
    __syncthreads();
#pragma unroll
    for (int mt = 0; mt < 4; mt++) {
#pragma unroll
        for (int rr = 0; rr < 2; rr++) {
            int row_local = mt * 16 + rr * 8 + r;
            float ts = 0.f, ts2 = 0.f;
#pragma unroll
            for (int w2 = 0; w2 < 8; w2++) {
                ts += red[row_local * 16 + w2 * 2 + 0];
                ts2 += red[row_local * 16 + w2 * 2 + 1];
            }
            float mu = ts * (1.0f / 256.0f);
            float var = ts2 * (1.0f / 256.0f) - mu * mu;
            float rs = rsqrtf(var + 1e-5f);
            int rg = r0 + row_local;
            int b_ = rg >> 15, t_ = (rg >> 8) & 127, n_ = rg & 255;
            float* orow = out + (((size_t)b_ * 256 + n_) * 128 + t_) * 256;
#pragma unroll
            for (int nt = 0; nt < 4; nt++) {
                int col = warp * 32 + nt * 8 + 2 * cl;
                float2 lg = *(const float2*)&ln_g[col];
                float2 lb = *(const float2*)&ln_b[col];
                float z0 = (acc[mt][nt][rr * 2 + 0] - mu) * rs * lg.x + lb.x;
                float z1 = (acc[mt][nt][rr * 2 + 1] - mu) * rs * lg.y + lb.y;
                *(float2*)&orow[col] = make_float2(gelu_f(z0), gelu_f(z1));
            }
        }
    }
}

extern "C" void kernel_launch(void* const* d_in, const int* in_sizes, int n_in,
                              void* d_out, int out_size) {
    const float* x       = (const float*)d_in[0];
    const float* A_list  = (const float*)d_in[1];
    const float* in_w    = (const float*)d_in[2];
    const float* in_b    = (const float*)d_in[3];
    const float* out_w   = (const float*)d_in[4];
    const float* out_b   = (const float*)d_in[5];
    const float* lag     = (const float*)d_in[6];
    const float* cw1     = (const float*)d_in[7];
    const float* cb1     = (const float*)d_in[8];
    const float* cw2     = (const float*)d_in[9];
    const float* cb2     = (const float*)d_in[10];
    const float* gw1     = (const float*)d_in[11];
    const float* gb1     = (const float*)d_in[12];
    const float* gw2     = (const float*)d_in[13];
    const float* gb2     = (const float*)d_in[14];
    const float* lng     = (const float*)d_in[15];
    const float* lnb     = (const float*)d_in[16];
    float* out = (float*)d_out;

    // Idempotent host-side attribute set (not a stream op -> graph-capture safe).
    cudaFuncSetAttribute(k_spatial_bf16, cudaFuncAttributeMaxDynamicSharedMemorySize, SP_SMEM);

    // Order chosen so k_spatial_bf16 is the 4th launch (ncu capture slot).
    k_h2<<<dim3(2, 2, 512), 256>>>(x, in_w, in_b);
    k_ctx_a<<<64, 256>>>(x);
    k_prepA<<<2048, 256>>>(A_list, lag, cw1, cb1, cw2, cb2, gw1, gb1, gw2, gb2);
    k_spatial_bf16<<<dim3(2, 512), 512, SP_SMEM>>>();
    k_owT<<<dim3(8, 8), dim3(32, 8)>>>(out_w);
    k_out_bf16<<<2048, 256>>>(out_b, lng, lnb, out);
}

// round 13
// speedup vs baseline: 1.2157x; 1.2157x over previous
#include <cuda_runtime.h>
#include <cuda_bf16.h>
#include <cstdint>
#include <math.h>

#define Bn 4
#define Nn 256
#define Tn 128
#define Fn 64
#define Kn 8
#define Hn 256

// ---------------- scratch (static device globals) ----------------
__device__ float g_ht[Bn*Tn*Nn*Hn];            // h: [b][t][n][h] fp32
__device__ __nv_bfloat16 g_aggbf[Bn*Tn*Nn*Hn]; // lag aggregate bf16: [bt*256+i][h]
__device__ __nv_bfloat16 g_AbfS[Bn*Kn*Nn*Nn];  // alpha-scaled normalized A bf16: [b][k][i][j]
__device__ __nv_bfloat16 g_hbfT[Bn*Tn*Hn*Nn];  // h bf16 transposed: [b][t][h][n]
__device__ __nv_bfloat16 g_owT[Hn*Hn];         // out_w transposed bf16: [o][h]
__device__ float g_part2[64*64];               // ctx partials: [(b*16+chunk)][f]

__device__ __forceinline__ float gelu_f(float v) {
    return 0.5f * v * (1.0f + erff(v * 0.7071067811865476f));
}

__device__ __forceinline__ uint32_t f2tf(float x) {
    uint32_t u;
    asm("cvt.rna.tf32.f32 %0, %1;" : "=r"(u) : "f"(x));
    return u;
}

__device__ __forceinline__ void mma_tf32(float (&d)[4], const uint32_t (&a)[4], const uint32_t (&b)[2]) {
    asm volatile(
        "mma.sync.aligned.m16n8k8.row.col.f32.tf32.tf32.f32 "
        "{%0,%1,%2,%3}, {%4,%5,%6,%7}, {%8,%9}, {%0,%1,%2,%3};"
        : "+f"(d[0]), "+f"(d[1]), "+f"(d[2]), "+f"(d[3])
        : "r"(a[0]), "r"(a[1]), "r"(a[2]), "r"(a[3]), "r"(b[0]), "r"(b[1]));
}

__device__ __forceinline__ void mma_bf16(float (&d)[4], const uint32_t (&a)[4], const uint32_t (&b)[2]) {
    asm volatile(
        "mma.sync.aligned.m16n8k16.row.col.f32.bf16.bf16.f32 "
        "{%0,%1,%2,%3}, {%4,%5,%6,%7}, {%8,%9}, {%0,%1,%2,%3};"
        : "+f"(d[0]), "+f"(d[1]), "+f"(d[2]), "+f"(d[3])
        : "r"(a[0]), "r"(a[1]), "r"(a[2]), "r"(a[3]), "r"(b[0]), "r"(b[1]));
}

__device__ __forceinline__ void ldsm_x4(uint32_t (&r)[4], uint32_t addr) {
    asm volatile("ldmatrix.sync.aligned.m8n8.x4.shared.b16 {%0,%1,%2,%3}, [%4];"
                 : "=r"(r[0]), "=r"(r[1]), "=r"(r[2]), "=r"(r[3]) : "r"(addr));
}

__device__ __forceinline__ uint32_t smem_u32(const void* p) {
    uint32_t a;
    asm("{ .reg .u64 t; cvta.to.shared.u64 t, %1; cvt.u32.u64 %0, t; }" : "=r"(a) : "l"(p));
    return a;
}

__device__ __forceinline__ void cp_async16(uint32_t dst, const void* src) {
    asm volatile("cp.async.cg.shared.global [%0], [%1], 16;" :: "r"(dst), "l"(src));
}

// swizzled byte offset, rows of 64B (4x16B chunks), 16B-chunk rotation
#define SWC(r, cb) (((r) << 6) + ((((((cb) >> 4) + (((r) >> 1) & 3))) & 3) << 4))
// swizzled byte offset, rows of 128B (8x16B chunks), rotate column by row
#define SWD(r, cb) (((r) << 7) + (((((cb) >> 4) + (r)) & 7) << 4))

// ---------------- ctx mean partials (grid 64 = b*16 + chunk) ----------------
__global__ __launch_bounds__(256) void k_ctx_a(const float* __restrict__ x) {
    int tid = threadIdx.x;
    int b = blockIdx.x >> 4, ch = blockIdx.x & 15;
    const float* base = x + (size_t)b * 2097152 + (size_t)ch * 131072;  // 2048 rows x 64 f
    int fg = tid & 15, rg = tid >> 4;
    float4 acc = make_float4(0.f, 0.f, 0.f, 0.f);
#pragma unroll 8
    for (int it = 0; it < 128; it++) {
        const float4 v = *(const float4*)(base + (size_t)(it * 16 + rg) * 64 + fg * 4);
        acc.x += v.x; acc.y += v.y; acc.z += v.z; acc.w += v.w;
    }
    __shared__ float4 sm[256];
    sm[tid] = acc;
    __syncthreads();
    if (tid < 16) {
        float4 t = make_float4(0.f, 0.f, 0.f, 0.f);
#pragma unroll
        for (int r2 = 0; r2 < 16; r2++) {
            float4 v = sm[r2 * 16 + tid];
            t.x += v.x; t.y += v.y; t.z += v.z; t.w += v.w;
        }
        *(float4*)&g_part2[blockIdx.x * 64 + tid * 4] = t;
    }
}

// ------ A row-normalize + (redundant per-block) gate MLP + alpha scale + bf16 cast ------
__global__ __launch_bounds__(256) void k_prepA(const float* __restrict__ A_list,
                       const float* __restrict__ lag_embed,
                       const float* __restrict__ cw1, const float* __restrict__ cb1,
                       const float* __restrict__ cw2, const float* __restrict__ cb2,
                       const float* __restrict__ gw1, const float* __restrict__ gb1,
                       const float* __restrict__ gw2, const float* __restrict__ gb2) {
    __shared__ float red[8];
    __shared__ float invs;
    __shared__ float ctx_sm[256];
    __shared__ float alpha_sm[4];
    int row = blockIdx.x;          // row = k*256 + i
    int tid = threadIdx.x;         // j
    float v = A_list[row * 256 + tid];
    float s = v;
#pragma unroll
    for (int o = 16; o > 0; o >>= 1) s += __shfl_xor_sync(0xffffffffu, s, o);
    if ((tid & 31) == 0) red[tid >> 5] = s;
    {   // ctx[b][f] from 16 chunk partials
        int b = tid >> 6, f = tid & 63;
        float cs = 0.f;
#pragma unroll
        for (int c = 0; c < 16; c++) cs += g_part2[(b * 16 + c) * 64 + f];
        ctx_sm[tid] = cs * (1.0f / 32768.0f);
    }
    __syncthreads();
    if (tid == 0) {
        float t = 0.f;
#pragma unroll
        for (int w = 0; w < 8; w++) t += red[w];
        invs = 1.0f / fmaxf(t, 1e-8f);
    }
    if (tid < 4) {                 // gate MLP for b = tid, k = row>>8
        int b = tid, kk = row >> 8;
        float e1[8];
#pragma unroll
        for (int e = 0; e < 8; e++) {
            float t = cb1[e];
            for (int f = 0; f < 64; f++) t += ctx_sm[b * 64 + f] * cw1[f * 8 + e];
            e1[e] = gelu_f(t);
        }
        float cf[8];
#pragma unroll
        for (int e2 = 0; e2 < 8; e2++) {
            float t = cb2[e2];
#pragma unroll
            for (int e = 0; e < 8; e++) t += e1[e] * cw2[e * 8 + e2];
            cf[e2] = t;
        }
        float gg[8];
#pragma unroll
        for (int e = 0; e < 8; e++) {
            float t = gb1[e];
#pragma unroll
            for (int i = 0; i < 16; i++) {
                float gi = (i < 8) ? lag_embed[kk * 8 + i] : cf[i - 8];
                t += gi * gw1[i * 8 + e];
            }
            gg[e] = gelu_f(t);
        }
        float o = gb2[0];
#pragma unroll
        for (int e = 0; e < 8; e++) o += gg[e] * gw2[e];
        alpha_sm[b] = 1.0f / (1.0f + expf(-o));
    }
    __syncthreads();
    float vn = v * invs;
    int k = row >> 8, i = row & 255;
#pragma unroll
    for (int b = 0; b < 4; b++) {
        g_AbfS[((size_t)(b * 8 + k) * 256 + i) * 256 + tid] = __float2bfloat16(alpha_sm[b] * vn);
    }
}

// ---------------- out_w transpose -> bf16 g_owT[o][h] ----------------
__global__ void k_owT(const float* __restrict__ out_w) {
    __shared__ float tile[32][33];
    int h0 = blockIdx.x * 32, o0 = blockIdx.y * 32;
    int tx = threadIdx.x, ty = threadIdx.y;
#pragma unroll
    for (int p = 0; p < 4; p++)
        tile[ty + p * 8][tx] = out_w[(h0 + ty + p * 8) * 256 + o0 + tx];
    __syncthreads();
#pragma unroll
    for (int p = 0; p < 4; p++)
        g_owT[(size_t)(o0 + ty + p * 8) * 256 + h0 + tx] = __float2bfloat16(tile[tx][ty + p * 8]);
}

// ---------------- K1: h = x@in_w + in_b (tf32 mma), write g_ht fp32 + g_hbfT bf16^T
union SmemH {
    struct { uint32_t As[32 * 132]; uint32_t Bs[32 * 132]; } g;
    __nv_bfloat16 tr[128 * 136];
};

__global__ __launch_bounds__(256) void k_h2(const float* __restrict__ x,
                                            const float* __restrict__ in_w,
                                            const float* __restrict__ in_b) {
    __shared__ SmemH sm;
    int tid = threadIdx.x, lane = tid & 31, warp = tid >> 5;
    int n0 = blockIdx.x * 128, h0 = blockIdx.y * 128;
    int bt = blockIdx.z, b = bt >> 7, t = bt & 127;
    int wm = warp & 1, wn = warp >> 1;     // warp tile 64(n-rows) x 32(h-cols)
    int r = lane >> 2, cl = lane & 3;

    float acc[4][4][4];
#pragma unroll
    for (int mt = 0; mt < 4; mt++)
#pragma unroll
        for (int nt = 0; nt < 4; nt++)
#pragma unroll
            for (int e = 0; e < 4; e++) acc[mt][nt][e] = 0.f;

    for (int f0 = 0; f0 < 64; f0 += 32) {
        __syncthreads();
        {   // x tile -> As[f][n] (tf32)
            int f = tid & 31, nb = tid >> 5;
            const float* xb = x + (((size_t)(b * 256 + n0) * 128 + t) * 64) + f0 + f;
#pragma unroll
            for (int p = 0; p < 16; p++) {
                int nn = nb + p * 8;
                sm.g.As[f * 132 + nn] = f2tf(xb[(size_t)nn * 8192]);
            }
        }
        {   // w tile -> Bs[f][h] (tf32)
#pragma unroll
            for (int p = 0; p < 16; p++) {
                int idx = tid + p * 256;
                int f = idx >> 7, c = idx & 127;
                sm.g.Bs[f * 132 + c] = f2tf(in_w[(f0 + f) * 256 + h0 + c]);
            }
        }
        __syncthreads();
#pragma unroll
        for (int ks = 0; ks < 4; ks++) {
            int ko = ks * 8;
            uint32_t a[4][4], bfr[4][2];
#pragma unroll
            for (int mt = 0; mt < 4; mt++) {
                int rb = wm * 64 + mt * 16 + r;
                a[mt][0] = sm.g.As[(ko + cl) * 132 + rb];
                a[mt][1] = sm.g.As[(ko + cl) * 132 + rb + 8];
                a[mt][2] = sm.g.As[(ko + 4 + cl) * 132 + rb];
                a[mt][3] = sm.g.As[(ko + 4 + cl) * 132 + rb + 8];
            }
#pragma unroll
            for (int nt = 0; nt < 4; nt++) {
                int nb2 = wn * 32 + nt * 8 + r;
                bfr[nt][0] = sm.g.Bs[(ko + cl) * 132 + nb2];
                bfr[nt][1] = sm.g.Bs[(ko + 4 + cl) * 132 + nb2];
            }
#pragma unroll
            for (int mt = 0; mt < 4; mt++)
#pragma unroll
                for (int nt = 0; nt < 4; nt++)
                    mma_tf32(acc[mt][nt], a[mt], bfr[nt]);
        }
    }

    // add bias, write fp32 g_ht (coalesced)
    float* Og = g_ht + (size_t)bt * 65536;
#pragma unroll
    for (int mt = 0; mt < 4; mt++) {
        int row = wm * 64 + mt * 16 + r;
#pragma unroll
        for (int nt = 0; nt < 4; nt++) {
            int col = wn * 32 + nt * 8 + 2 * cl;
            float2 ob = *(const float2*)&in_b[h0 + col];
            acc[mt][nt][0] += ob.x;  acc[mt][nt][1] += ob.y;
            acc[mt][nt][2] += ob.x;  acc[mt][nt][3] += ob.y;
            *(float2*)(Og + (size_t)(n0 + row) * 256 + h0 + col)     = make_float2(acc[mt][nt][0], acc[mt][nt][1]);
            *(float2*)(Og + (size_t)(n0 + row + 8) * 256 + h0 + col) = make_float2(acc[mt][nt][2], acc[mt][nt][3]);
        }
    }

    // stage bf16 transpose in smem: tr[h][n]
    __syncthreads();
#pragma unroll
    for (int mt = 0; mt < 4; mt++) {
        int row = wm * 64 + mt * 16 + r;
#pragma unroll
        for (int nt = 0; nt < 4; nt++) {
            int col = wn * 32 + nt * 8 + 2 * cl;
            sm.tr[(col)     * 136 + row]     = __float2bfloat16(acc[mt][nt][0]);
            sm.tr[(col + 1) * 136 + row]     = __float2bfloat16(acc[mt][nt][1]);
            sm.tr[(col)     * 136 + row + 8] = __float2bfloat16(acc[mt][nt][2]);
            sm.tr[(col + 1) * 136 + row + 8] = __float2bfloat16(acc[mt][nt][3]);
        }
    }
    __syncthreads();
    __nv_bfloat16* Dst = g_hbfT + (size_t)bt * 65536;
#pragma unroll
    for (int p = 0; p < 32; p++) {
        int idx = tid + p * 256;
        int h = idx >> 6, np = idx & 63;
        uint32_t v = *(uint32_t*)&sm.tr[h * 136 + np * 2];
        *(uint32_t*)(Dst + (size_t)(h0 + h) * 256 + n0 + np * 2) = v;
    }
}

// ---------------- K2: bf16 mma GEMM, 128x128 CTA, K-chunk 64, 2-stage dynamic smem ----
// Stage = A (128 rows x 128B, swizzled) + B (128 rows x 128B) = 32 KB. 2 stages = 64 KB.
#define SP_STAGE 32768
#define SP_SMEM  (2 * SP_STAGE)   // 65536 bytes dynamic; 2 CTAs/SM -> 128 KB

__global__ __launch_bounds__(256, 2) void k_spatial_bf16() {
    extern __shared__ __align__(16) char smem[];
    int tid = threadIdx.x, lane = tid & 31, warp = tid >> 5;
    int i0 = blockIdx.x * 128, h0 = blockIdx.y * 128;
    int bt = blockIdx.z, b = bt >> 7, t = bt & 127;
    int wm = warp & 1, wn = warp >> 1;    // warp tile 64(m) x 32(n)

    float acc[4][4][4];
#pragma unroll
    for (int mt = 0; mt < 4; mt++)
#pragma unroll
        for (int nt = 0; nt < 4; nt++)
#pragma unroll
            for (int e = 0; e < 4; e++) acc[mt][nt][e] = 0.f;

    int nlag = (t + 1 < 8) ? (t + 1) : 8;
    int nch = nlag * 4;                   // 64-K chunks

    const char* Ab = (const char*)g_AbfS + (size_t)b * 8 * 131072 + (size_t)i0 * 512;
    const char* Hb = (const char*)g_hbfT + (size_t)(b * 128 + t) * 131072 + (size_t)h0 * 512;

    uint32_t sbase = smem_u32(smem);

    // loader: 4 passes x 256 threads cover 128 rows x 8 chunks of 16B (per tile)
    auto issue = [&](int c, int s) {
        int lag = c >> 2, j0b = (c & 3) * 128;
        const char* asrc = Ab + (size_t)lag * 131072 + j0b;
        const char* bsrc = Hb - (size_t)lag * 131072 + j0b;
        uint32_t sa = sbase + s * SP_STAGE;
        uint32_t sb = sa + 16384;
#pragma unroll
        for (int p = 0; p < 4; p++) {
            int idx = tid + p * 256;
            int row = idx >> 3, cb = (idx & 7) * 16;
            uint32_t sw = SWD(row, cb);
            int gb = row * 512 + cb;
            cp_async16(sa + sw, asrc + gb);
            cp_async16(sb + sw, bsrc + gb);
        }
        asm volatile("cp.async.commit_group;" ::: "memory");
    };

    issue(0, 0);

    int arow = wm * 64 + (lane & 15);
    int akb = (lane >> 4) * 16;
    int brow = wn * 32 + (lane & 7) + (lane >> 4) * 8;
    int bkb = ((lane >> 3) & 1) * 16;

    for (int c = 0; c < nch; ++c) {
        int s = c & 1;
        asm volatile("cp.async.wait_group 0;" ::: "memory");
        __syncthreads();
        if (c + 1 < nch) issue(c + 1, s ^ 1);
        uint32_t sa = sbase + s * SP_STAGE;
        uint32_t sb = sa + 16384;
#pragma unroll
        for (int ks = 0; ks < 4; ks++) {
            uint32_t a[4][4];
#pragma unroll
            for (int mt = 0; mt < 4; mt++)
                ldsm_x4(a[mt], sa + SWD(arow + mt * 16, ks * 32 + akb));
            uint32_t bb[2][4];
#pragma unroll
            for (int np = 0; np < 2; np++)
                ldsm_x4(bb[np], sb + SWD(brow + np * 16, ks * 32 + bkb));
#pragma unroll
            for (int mt = 0; mt < 4; mt++)
#pragma unroll
                for (int nt = 0; nt < 4; nt++) {
                    uint32_t bfr[2] = { bb[nt >> 1][(nt & 1) * 2], bb[nt >> 1][(nt & 1) * 2 + 1] };
                    mma_bf16(acc[mt][nt], a[mt], bfr);
                }
        }
        __syncthreads();
    }

    int r = lane >> 2, cl = lane & 3;
    __nv_bfloat16* Og = g_aggbf + (size_t)bt * 65536;
#pragma unroll
    for (int mt = 0; mt < 4; mt++) {
        int row = i0 + wm * 64 + mt * 16 + r;
#pragma unroll
        for (int nt = 0; nt < 4; nt++) {
            int col = h0 + wn * 32 + nt * 8 + 2 * cl;
            __nv_bfloat162 v0 = make_bfloat162(__float2bfloat16(acc[mt][nt][0]), __float2bfloat16(acc[mt][nt][1]));
            __nv_bfloat162 v1 = make_bfloat162(__float2bfloat16(acc[mt][nt][2]), __float2bfloat16(acc[mt][nt][3]));
            *(__nv_bfloat162*)(Og + (size_t)row * 256 + col)       = v0;
            *(__nv_bfloat162*)(Og + (size_t)(row + 8) * 256 + col) = v1;
        }
    }
}

// ---------------- K3: out2 = agg@out_w (bf16 mma); +out_b +h; LN; GELU; transpose
__global__ __launch_bounds__(256) void k_out_bf16(const float* __restrict__ out_b,
                                                  const float* __restrict__ ln_g,
                                                  const float* __restrict__ ln_b,
                                                  float* __restrict__ out) {
    __shared__ __align__(16) char sA[2][4096];    // 64 rows x 64B
    __shared__ __align__(16) char sB[2][16384];   // 256 rows(o) x 64B
    __shared__ float red[64 * 16];                // [row][warp][s,s2]
    int tid = threadIdx.x, lane = tid & 31, warp = tid >> 5;
    int r0 = blockIdx.x * 64;                     // rows = bt*256 + n
    int r = lane >> 2, cl = lane & 3;

    float acc[4][4][4];
#pragma unroll
    for (int mt = 0; mt < 4; mt++)
#pragma unroll
        for (int nt = 0; nt < 4; nt++)
#pragma unroll
            for (int e = 0; e < 4; e++) acc[mt][nt][e] = 0.f;

    uint32_t sAb[2] = { smem_u32(sA[0]), smem_u32(sA[1]) };
    uint32_t sBb[2] = { smem_u32(sB[0]), smem_u32(sB[1]) };

    const char* Abase = (const char*)g_aggbf + (size_t)r0 * 512;
    const char* Bbase = (const char*)g_owT;

    int lrow = tid >> 2, lcb = (tid & 3) * 16;
    int lswz = SWC(lrow, lcb);

    auto issue = [&](int c, int s) {
        int j0b = c * 64;
        cp_async16(sAb[s] + lswz, Abase + (size_t)lrow * 512 + j0b + lcb);
#pragma unroll
        for (int p = 0; p < 4; p++) {
            int row = lrow + p * 64;
            cp_async16(sBb[s] + SWC(row, lcb), Bbase + (size_t)row * 512 + j0b + lcb);
        }
        asm volatile("cp.async.commit_group;" ::: "memory");
    };

    issue(0, 0);
    issue(1, 1);

    int arow = lane & 15;
    int akb = (lane >> 4) * 16;
    int brow = warp * 32 + (lane & 7) + (lane >> 4) * 8;
    int bkb = ((lane >> 3) & 1) * 16;

    for (int c = 0; c < 8; ++c) {
        int s = c & 1;
        if (c == 7) asm volatile("cp.async.wait_group 0;" ::: "memory");
        else        asm volatile("cp.async.wait_group 1;" ::: "memory");
        __syncthreads();
#pragma unroll
        for (int ks = 0; ks < 2; ks++) {
            uint32_t a[4][4];
#pragma unroll
            for (int mt = 0; mt < 4; mt++)
                ldsm_x4(a[mt], sAb[s] + SWC(arow + mt * 16, ks * 32 + akb));
            uint32_t bb[2][4];
#pragma unroll
            for (int np = 0; np < 2; np++)
                ldsm_x4(bb[np], sBb[s] + SWC(brow + np * 16, ks * 32 + bkb));
#pragma unroll
            for (int mt = 0; mt < 4; mt++)
#pragma unroll
                for (int nt = 0; nt < 4; nt++) {
                    uint32_t bfr[2] = { bb[nt >> 1][(nt & 1) * 2], bb[nt >> 1][(nt & 1) * 2 + 1] };
                    mma_bf16(acc[mt][nt], a[mt], bfr);
                }
        }
        __syncthreads();
        if (c + 2 < 8) issue(c + 2, s);
    }

    // epilogue: residual + LN stats.  rows: mt*16 + rr*8 + r ; cols: warp*32 + nt*8 + 2cl
#pragma unroll
    for (int mt = 0; mt < 4; mt++) {
#pragma unroll
        for (int rr = 0; rr < 2; rr++) {
            int row_local = mt * 16 + rr * 8 + r;
            size_t rg = (size_t)r0 + row_local;
            const float* hrow = g_ht + rg * 256;
            float ss = 0.f, ss2 = 0.f;
#pragma unroll
            for (int nt = 0; nt < 4; nt++) {
                int col = warp * 32 + nt * 8 + 2 * cl;
                float2 hb = *(const float2*)&hrow[col];
                float2 ob = *(const float2*)&out_b[col];
                float v0 = acc[mt][nt][rr * 2 + 0] + ob.x + hb.x;
                float v1 = acc[mt][nt][rr * 2 + 1] + ob.y + hb.y;
                acc[mt][nt][rr * 2 + 0] = v0;
                acc[mt][nt][rr * 2 + 1] = v1;
                ss += v0 + v1;
                ss2 += v0 * v0 + v1 * v1;
            }
            ss += __shfl_xor_sync(0xffffffffu, ss, 1);
            ss2 += __shfl_xor_sync(0xffffffffu, ss2, 1);
            ss += __shfl_xor_sync(0xffffffffu, ss, 2);
            ss2 += __shfl_xor_sync(0xffffffffu, ss2, 2);
            if (cl == 0) {
                red[row_local * 16 + warp * 2 + 0] = ss;
                red[row_local * 16 + warp * 2 + 1] = ss2;
            }
        }
    }
    __syncthreads();
#pragma unroll
    for (int mt = 0; mt < 4; mt++) {
#pragma unroll
        for (int rr = 0; rr < 2; rr++) {
            int row_local = mt * 16 + rr * 8 + r;
            float ts = 0.f, ts2 = 0.f;
#pragma unroll
            for (int w2 = 0; w2 < 8; w2++) {
                ts += red[row_local * 16 + w2 * 2 + 0];
                ts2 += red[row_local * 16 + w2 * 2 + 1];
            }
            float mu = ts * (1.0f / 256.0f);
            float var = ts2 * (1.0f / 256.0f) - mu * mu;
            float rs = rsqrtf(var + 1e-5f);
            int rg = r0 + row_local;
            int b_ = rg >> 15, t_ = (rg >> 8) & 127, n_ = rg & 255;
            float* orow = out + (((size_t)b_ * 256 + n_) * 128 + t_) * 256;
#pragma unroll
            for (int nt = 0; nt < 4; nt++) {
                int col = warp * 32 + nt * 8 + 2 * cl;
                float2 lg = *(const float2*)&ln_g[col];
                float2 lb = *(const float2*)&ln_b[col];
                float z0 = (acc[mt][nt][rr * 2 + 0] - mu) * rs * lg.x + lb.x;
                float z1 = (acc[mt][nt][rr * 2 + 1] - mu) * rs * lg.y + lb.y;
                *(float2*)&orow[col] = make_float2(gelu_f(z0), gelu_f(z1));
            }
        }
    }
}

extern "C" void kernel_launch(void* const* d_in, const int* in_sizes, int n_in,
                              void* d_out, int out_size) {
    const float* x       = (const float*)d_in[0];
    const float* A_list  = (const float*)d_in[1];
    const float* in_w    = (const float*)d_in[2];
    const float* in_b    = (const float*)d_in[3];
    const float* out_w   = (const float*)d_in[4];
    const float* out_b   = (const float*)d_in[5];
    const float* lag     = (const float*)d_in[6];
    const float* cw1     = (const float*)d_in[7];
    const float* cb1     = (const float*)d_in[8];
    const float* cw2     = (const float*)d_in[9];
    const float* cb2     = (const float*)d_in[10];
    const float* gw1     = (const float*)d_in[11];
    const float* gb1     = (const float*)d_in[12];
    const float* gw2     = (const float*)d_in[13];
    const float* gb2     = (const float*)d_in[14];
    const float* lng     = (const float*)d_in[15];
    const float* lnb     = (const float*)d_in[16];
    float* out = (float*)d_out;

    // Idempotent host-side attribute set (not a stream op -> graph-capture safe).
    cudaFuncSetAttribute(k_spatial_bf16, cudaFuncAttributeMaxDynamicSharedMemorySize, SP_SMEM);

    // Order chosen so k_spatial_bf16 is the 4th launch (ncu capture slot).
    k_h2<<<dim3(2, 2, 512), 256>>>(x, in_w, in_b);
    k_ctx_a<<<64, 256>>>(x);
    k_prepA<<<2048, 256>>>(A_list, lag, cw1, cb1, cw2, cb2, gw1, gb1, gw2, gb2);
    k_spatial_bf16<<<dim3(2, 2, 512), 256, SP_SMEM>>>();
    k_owT<<<dim3(8, 8), dim3(32, 8)>>>(out_w);
    k_out_bf16<<<2048, 256>>>(out_b, lng, lnb, out);
}

// round 14
// speedup vs baseline: 1.3002x; 1.0695x over previous
#include <cuda_runtime.h>
#include <cuda_bf16.h>
#include <cstdint>
#include <math.h>

#define Bn 4
#define Nn 256
#define Tn 128
#define Fn 64
#define Kn 8
#define Hn 256

// ---------------- scratch (static device globals) ----------------
__device__ float g_ht[Bn*Tn*Nn*Hn];            // h: [b][t][n][h] fp32
__device__ __nv_bfloat16 g_aggbf[Bn*Tn*Nn*Hn]; // lag aggregate bf16: [bt*256+i][h]
__device__ __nv_bfloat16 g_AbfS[Bn*Kn*Nn*Nn];  // alpha-scaled normalized A bf16: [b][k][i][j]
__device__ __nv_bfloat16 g_hbfT[Bn*Tn*Hn*Nn];  // h bf16 transposed: [b][t][h][n]
__device__ __nv_bfloat16 g_owT[Hn*Hn];         // out_w transposed bf16: [o][h]
__device__ float g_part2[64*64];               // ctx partials: [(b*16+chunk)][f]

__device__ __forceinline__ float gelu_f(float v) {
    return 0.5f * v * (1.0f + erff(v * 0.7071067811865476f));
}

__device__ __forceinline__ uint32_t f2tf(float x) {
    uint32_t u;
    asm("cvt.rna.tf32.f32 %0, %1;" : "=r"(u) : "f"(x));
    return u;
}

__device__ __forceinline__ void mma_tf32(float (&d)[4], const uint32_t (&a)[4], const uint32_t (&b)[2]) {
    asm volatile(
        "mma.sync.aligned.m16n8k8.row.col.f32.tf32.tf32.f32 "
        "{%0,%1,%2,%3}, {%4,%5,%6,%7}, {%8,%9}, {%0,%1,%2,%3};"
        : "+f"(d[0]), "+f"(d[1]), "+f"(d[2]), "+f"(d[3])
        : "r"(a[0]), "r"(a[1]), "r"(a[2]), "r"(a[3]), "r"(b[0]), "r"(b[1]));
}

__device__ __forceinline__ void mma_bf16(float (&d)[4], const uint32_t (&a)[4], const uint32_t (&b)[2]) {
    asm volatile(
        "mma.sync.aligned.m16n8k16.row.col.f32.bf16.bf16.f32 "
        "{%0,%1,%2,%3}, {%4,%5,%6,%7}, {%8,%9}, {%0,%1,%2,%3};"
        : "+f"(d[0]), "+f"(d[1]), "+f"(d[2]), "+f"(d[3])
        : "r"(a[0]), "r"(a[1]), "r"(a[2]), "r"(a[3]), "r"(b[0]), "r"(b[1]));
}

__device__ __forceinline__ void ldsm_x4(uint32_t (&r)[4], uint32_t addr) {
    asm volatile("ldmatrix.sync.aligned.m8n8.x4.shared.b16 {%0,%1,%2,%3}, [%4];"
                 : "=r"(r[0]), "=r"(r[1]), "=r"(r[2]), "=r"(r[3]) : "r"(addr));
}

__device__ __forceinline__ uint32_t smem_u32(const void* p) {
    uint32_t a;
    asm("{ .reg .u64 t; cvta.to.shared.u64 t, %1; cvt.u32.u64 %0, t; }" : "=r"(a) : "l"(p));
    return a;
}

__device__ __forceinline__ void cp_async16(uint32_t dst, const void* src) {
    asm volatile("cp.async.cg.shared.global [%0], [%1], 16;" :: "r"(dst), "l"(src));
}

// swizzled byte offset, rows of 128B (8x16B chunks), rotate column by row
#define SWD(r, cb) (((r) << 7) + (((((cb) >> 4) + (r)) & 7) << 4))

// ---------------- ctx mean partials (grid 64 = b*16 + chunk) ----------------
__global__ __launch_bounds__(256) void k_ctx_a(const float* __restrict__ x) {
    int tid = threadIdx.x;
    int b = blockIdx.x >> 4, ch = blockIdx.x & 15;
    const float* base = x + (size_t)b * 2097152 + (size_t)ch * 131072;  // 2048 rows x 64 f
    int fg = tid & 15, rg = tid >> 4;
    float4 acc = make_float4(0.f, 0.f, 0.f, 0.f);
#pragma unroll 8
    for (int it = 0; it < 128; it++) {
        const float4 v = *(const float4*)(base + (size_t)(it * 16 + rg) * 64 + fg * 4);
        acc.x += v.x; acc.y += v.y; acc.z += v.z; acc.w += v.w;
    }
    __shared__ float4 sm[256];
    sm[tid] = acc;
    __syncthreads();
    if (tid < 16) {
        float4 t = make_float4(0.f, 0.f, 0.f, 0.f);
#pragma unroll
        for (int r2 = 0; r2 < 16; r2++) {
            float4 v = sm[r2 * 16 + tid];
            t.x += v.x; t.y += v.y; t.z += v.z; t.w += v.w;
        }
        *(float4*)&g_part2[blockIdx.x * 64 + tid * 4] = t;
    }
}

// ------ A row-normalize + (redundant per-block) gate MLP + alpha scale + bf16 cast ------
__global__ __launch_bounds__(256) void k_prepA(const float* __restrict__ A_list,
                       const float* __restrict__ lag_embed,
                       const float* __restrict__ cw1, const float* __restrict__ cb1,
                       const float* __restrict__ cw2, const float* __restrict__ cb2,
                       const float* __restrict__ gw1, const float* __restrict__ gb1,
                       const float* __restrict__ gw2, const float* __restrict__ gb2) {
    __shared__ float red[8];
    __shared__ float invs;
    __shared__ float ctx_sm[256];
    __shared__ float alpha_sm[4];
    int row = blockIdx.x;          // row = k*256 + i
    int tid = threadIdx.x;         // j
    float v = A_list[row * 256 + tid];
    float s = v;
#pragma unroll
    for (int o = 16; o > 0; o >>= 1) s += __shfl_xor_sync(0xffffffffu, s, o);
    if ((tid & 31) == 0) red[tid >> 5] = s;
    {   // ctx[b][f] from 16 chunk partials
        int b = tid >> 6, f = tid & 63;
        float cs = 0.f;
#pragma unroll
        for (int c = 0; c < 16; c++) cs += g_part2[(b * 16 + c) * 64 + f];
        ctx_sm[tid] = cs * (1.0f / 32768.0f);
    }
    __syncthreads();
    if (tid == 0) {
        float t = 0.f;
#pragma unroll
        for (int w = 0; w < 8; w++) t += red[w];
        invs = 1.0f / fmaxf(t, 1e-8f);
    }
    if (tid < 4) {                 // gate MLP for b = tid, k = row>>8
        int b = tid, kk = row >> 8;
        float e1[8];
#pragma unroll
        for (int e = 0; e < 8; e++) {
            float t = cb1[e];
            for (int f = 0; f < 64; f++) t += ctx_sm[b * 64 + f] * cw1[f * 8 + e];
            e1[e] = gelu_f(t);
        }
        float cf[8];
#pragma unroll
        for (int e2 = 0; e2 < 8; e2++) {
            float t = cb2[e2];
#pragma unroll
            for (int e = 0; e < 8; e++) t += e1[e] * cw2[e * 8 + e2];
            cf[e2] = t;
        }
        float gg[8];
#pragma unroll
        for (int e = 0; e < 8; e++) {
            float t = gb1[e];
#pragma unroll
            for (int i = 0; i < 16; i++) {
                float gi = (i < 8) ? lag_embed[kk * 8 + i] : cf[i - 8];
                t += gi * gw1[i * 8 + e];
            }
            gg[e] = gelu_f(t);
        }
        float o = gb2[0];
#pragma unroll
        for (int e = 0; e < 8; e++) o += gg[e] * gw2[e];
        alpha_sm[b] = 1.0f / (1.0f + expf(-o));
    }
    __syncthreads();
    float vn = v * invs;
    int k = row >> 8, i = row & 255;
#pragma unroll
    for (int b = 0; b < 4; b++) {
        g_AbfS[((size_t)(b * 8 + k) * 256 + i) * 256 + tid] = __float2bfloat16(alpha_sm[b] * vn);
    }
}

// ---------------- out_w transpose -> bf16 g_owT[o][h] ----------------
__global__ void k_owT(const float* __restrict__ out_w) {
    __shared__ float tile[32][33];
    int h0 = blockIdx.x * 32, o0 = blockIdx.y * 32;
    int tx = threadIdx.x, ty = threadIdx.y;
#pragma unroll
    for (int p = 0; p < 4; p++)
        tile[ty + p * 8][tx] = out_w[(h0 + ty + p * 8) * 256 + o0 + tx];
    __syncthreads();
#pragma unroll
    for (int p = 0; p < 4; p++)
        g_owT[(size_t)(o0 + ty + p * 8) * 256 + h0 + tx] = __float2bfloat16(tile[tx][ty + p * 8]);
}

// ---------------- K1: h = x@in_w + in_b (tf32 mma), write g_ht fp32 + g_hbfT bf16^T
union SmemH {
    struct { uint32_t As[32 * 132]; uint32_t Bs[32 * 132]; } g;
    __nv_bfloat16 tr[128 * 136];
};

__global__ __launch_bounds__(256) void k_h2(const float* __restrict__ x,
                                            const float* __restrict__ in_w,
                                            const float* __restrict__ in_b) {
    __shared__ SmemH sm;
    int tid = threadIdx.x, lane = tid & 31, warp = tid >> 5;
    int n0 = blockIdx.x * 128, h0 = blockIdx.y * 128;
    int bt = blockIdx.z, b = bt >> 7, t = bt & 127;
    int wm = warp & 1, wn = warp >> 1;     // warp tile 64(n-rows) x 32(h-cols)
    int r = lane >> 2, cl = lane & 3;

    float acc[4][4][4];
#pragma unroll
    for (int mt = 0; mt < 4; mt++)
#pragma unroll
        for (int nt = 0; nt < 4; nt++)
#pragma unroll
            for (int e = 0; e < 4; e++) acc[mt][nt][e] = 0.f;

    for (int f0 = 0; f0 < 64; f0 += 32) {
        __syncthreads();
        {   // x tile -> As[f][n] (tf32)
            int f = tid & 31, nb = tid >> 5;
            const float* xb = x + (((size_t)(b * 256 + n0) * 128 + t) * 64) + f0 + f;
#pragma unroll
            for (int p = 0; p < 16; p++) {
                int nn = nb + p * 8;
                sm.g.As[f * 132 + nn] = f2tf(xb[(size_t)nn * 8192]);
            }
        }
        {   // w tile -> Bs[f][h] (tf32)
#pragma unroll
            for (int p = 0; p < 16; p++) {
                int idx = tid + p * 256;
                int f = idx >> 7, c = idx & 127;
                sm.g.Bs[f * 132 + c] = f2tf(in_w[(f0 + f) * 256 + h0 + c]);
            }
        }
        __syncthreads();
#pragma unroll
        for (int ks = 0; ks < 4; ks++) {
            int ko = ks * 8;
            uint32_t a[4][4], bfr[4][2];
#pragma unroll
            for (int mt = 0; mt < 4; mt++) {
                int rb = wm * 64 + mt * 16 + r;
                a[mt][0] = sm.g.As[(ko + cl) * 132 + rb];
                a[mt][1] = sm.g.As[(ko + cl) * 132 + rb + 8];
                a[mt][2] = sm.g.As[(ko + 4 + cl) * 132 + rb];
                a[mt][3] = sm.g.As[(ko + 4 + cl) * 132 + rb + 8];
            }
#pragma unroll
            for (int nt = 0; nt < 4; nt++) {
                int nb2 = wn * 32 + nt * 8 + r;
                bfr[nt][0] = sm.g.Bs[(ko + cl) * 132 + nb2];
                bfr[nt][1] = sm.g.Bs[(ko + 4 + cl) * 132 + nb2];
            }
#pragma unroll
            for (int mt = 0; mt < 4; mt++)
#pragma unroll
                for (int nt = 0; nt < 4; nt++)
                    mma_tf32(acc[mt][nt], a[mt], bfr[nt]);
        }
    }

    // add bias, write fp32 g_ht (coalesced)
    float* Og = g_ht + (size_t)bt * 65536;
#pragma unroll
    for (int mt = 0; mt < 4; mt++) {
        int row = wm * 64 + mt * 16 + r;
#pragma unroll
        for (int nt = 0; nt < 4; nt++) {
            int col = wn * 32 + nt * 8 + 2 * cl;
            float2 ob = *(const float2*)&in_b[h0 + col];
            acc[mt][nt][0] += ob.x;  acc[mt][nt][1] += ob.y;
            acc[mt][nt][2] += ob.x;  acc[mt][nt][3] += ob.y;
            *(float2*)(Og + (size_t)(n0 + row) * 256 + h0 + col)     = make_float2(acc[mt][nt][0], acc[mt][nt][1]);
            *(float2*)(Og + (size_t)(n0 + row + 8) * 256 + h0 + col) = make_float2(acc[mt][nt][2], acc[mt][nt][3]);
        }
    }

    // stage bf16 transpose in smem: tr[h][n]
    __syncthreads();
#pragma unroll
    for (int mt = 0; mt < 4; mt++) {
        int row = wm * 64 + mt * 16 + r;
#pragma unroll
        for (int nt = 0; nt < 4; nt++) {
            int col = wn * 32 + nt * 8 + 2 * cl;
            sm.tr[(col)     * 136 + row]     = __float2bfloat16(acc[mt][nt][0]);
            sm.tr[(col + 1) * 136 + row]     = __float2bfloat16(acc[mt][nt][1]);
            sm.tr[(col)     * 136 + row + 8] = __float2bfloat16(acc[mt][nt][2]);
            sm.tr[(col + 1) * 136 + row + 8] = __float2bfloat16(acc[mt][nt][3]);
        }
    }
    __syncthreads();
    __nv_bfloat16* Dst = g_hbfT + (size_t)bt * 65536;
#pragma unroll
    for (int p = 0; p < 32; p++) {
        int idx = tid + p * 256;
        int h = idx >> 6, np = idx & 63;
        uint32_t v = *(uint32_t*)&sm.tr[h * 136 + np * 2];
        *(uint32_t*)(Dst + (size_t)(h0 + h) * 256 + n0 + np * 2) = v;
    }
}

// ---------------- K2: bf16 mma GEMM, 128x128 CTA, K-chunk 64, 2-stage dynamic smem ----
#define SP_STAGE 32768
#define SP_SMEM  (2 * SP_STAGE)   // 65536 bytes dynamic; 2 CTAs/SM -> 128 KB

__global__ __launch_bounds__(256, 2) void k_spatial_bf16() {
    extern __shared__ __align__(16) char smem[];
    int tid = threadIdx.x, lane = tid & 31, warp = tid >> 5;
    int i0 = blockIdx.x * 128, h0 = blockIdx.y * 128;
    int bt = blockIdx.z, b = bt >> 7, t = bt & 127;
    int wm = warp & 1, wn = warp >> 1;    // warp tile 64(m) x 32(n)

    float acc[4][4][4];
#pragma unroll
    for (int mt = 0; mt < 4; mt++)
#pragma unroll
        for (int nt = 0; nt < 4; nt++)
#pragma unroll
            for (int e = 0; e < 4; e++) acc[mt][nt][e] = 0.f;

    int nlag = (t + 1 < 8) ? (t + 1) : 8;
    int nch = nlag * 4;                   // 64-K chunks

    const char* Ab = (const char*)g_AbfS + (size_t)b * 8 * 131072 + (size_t)i0 * 512;
    const char* Hb = (const char*)g_hbfT + (size_t)(b * 128 + t) * 131072 + (size_t)h0 * 512;

    uint32_t sbase = smem_u32(smem);

    auto issue = [&](int c, int s) {
        int lag = c >> 2, j0b = (c & 3) * 128;
        const char* asrc = Ab + (size_t)lag * 131072 + j0b;
        const char* bsrc = Hb - (size_t)lag * 131072 + j0b;
        uint32_t sa = sbase + s * SP_STAGE;
        uint32_t sb = sa + 16384;
#pragma unroll
        for (int p = 0; p < 4; p++) {
            int idx = tid + p * 256;
            int row = idx >> 3, cb = (idx & 7) * 16;
            uint32_t sw = SWD(row, cb);
            int gb = row * 512 + cb;
            cp_async16(sa + sw, asrc + gb);
            cp_async16(sb + sw, bsrc + gb);
        }
        asm volatile("cp.async.commit_group;" ::: "memory");
    };

    issue(0, 0);

    int arow = wm * 64 + (lane & 15);
    int akb = (lane >> 4) * 16;
    int brow = wn * 32 + (lane & 7) + (lane >> 4) * 8;
    int bkb = ((lane >> 3) & 1) * 16;

    for (int c = 0; c < nch; ++c) {
        int s = c & 1;
        asm volatile("cp.async.wait_group 0;" ::: "memory");
        __syncthreads();
        if (c + 1 < nch) issue(c + 1, s ^ 1);
        uint32_t sa = sbase + s * SP_STAGE;
        uint32_t sb = sa + 16384;
#pragma unroll
        for (int ks = 0; ks < 4; ks++) {
            uint32_t a[4][4];
#pragma unroll
            for (int mt = 0; mt < 4; mt++)
                ldsm_x4(a[mt], sa + SWD(arow + mt * 16, ks * 32 + akb));
            uint32_t bb[2][4];
#pragma unroll
            for (int np = 0; np < 2; np++)
                ldsm_x4(bb[np], sb + SWD(brow + np * 16, ks * 32 + bkb));
#pragma unroll
            for (int mt = 0; mt < 4; mt++)
#pragma unroll
                for (int nt = 0; nt < 4; nt++) {
                    uint32_t bfr[2] = { bb[nt >> 1][(nt & 1) * 2], bb[nt >> 1][(nt & 1) * 2 + 1] };
                    mma_bf16(acc[mt][nt], a[mt], bfr);
                }
        }
        __syncthreads();
    }

    int r = lane >> 2, cl = lane & 3;
    __nv_bfloat16* Og = g_aggbf + (size_t)bt * 65536;
#pragma unroll
    for (int mt = 0; mt < 4; mt++) {
        int row = i0 + wm * 64 + mt * 16 + r;
#pragma unroll
        for (int nt = 0; nt < 4; nt++) {
            int col = h0 + wn * 32 + nt * 8 + 2 * cl;
            __nv_bfloat162 v0 = make_bfloat162(__float2bfloat16(acc[mt][nt][0]), __float2bfloat16(acc[mt][nt][1]));
            __nv_bfloat162 v1 = make_bfloat162(__float2bfloat16(acc[mt][nt][2]), __float2bfloat16(acc[mt][nt][3]));
            *(__nv_bfloat162*)(Og + (size_t)row * 256 + col)       = v0;
            *(__nv_bfloat162*)(Og + (size_t)(row + 8) * 256 + col) = v1;
        }
    }
}

// ---------------- K3: out2 = agg@out_w (bf16 mma, K-chunk 64, 2-stage); +out_b +h; LN; GELU
// Stage = A (64 rows x 128B) + B (256 rows x 128B) = 40 KB. 2 stages = 80 KB dynamic.
#define KO_ASZ   8192
#define KO_STAGE 40960
#define KO_SMEM  (2 * KO_STAGE)   // 81920 bytes; 2 CTAs/SM -> 160 KB

__global__ __launch_bounds__(256, 2) void k_out_bf16(const float* __restrict__ out_b,
                                                     const float* __restrict__ ln_g,
                                                     const float* __restrict__ ln_b,
                                                     float* __restrict__ out) {
    extern __shared__ __align__(16) char smem[];
    __shared__ float red[64 * 16];                // [row][warp][s,s2]
    int tid = threadIdx.x, lane = tid & 31, warp = tid >> 5;
    int r0 = blockIdx.x * 64;                     // rows = bt*256 + n
    int r = lane >> 2, cl = lane & 3;

    float acc[4][4][4];
#pragma unroll
    for (int mt = 0; mt < 4; mt++)
#pragma unroll
        for (int nt = 0; nt < 4; nt++)
#pragma unroll
            for (int e = 0; e < 4; e++) acc[mt][nt][e] = 0.f;

    uint32_t sbase = smem_u32(smem);
    const char* Abase = (const char*)g_aggbf + (size_t)r0 * 512;
    const char* Bbase = (const char*)g_owT;

    // loader per 64-K chunk: A 64 rows x 8x16B = 512 units (2/thread);
    // B 256 rows x 8x16B = 2048 units (8/thread).
    auto issue = [&](int c, int s) {
        int j0b = c * 128;
        uint32_t sa = sbase + s * KO_STAGE;
        uint32_t sb = sa + KO_ASZ;
#pragma unroll
        for (int p = 0; p < 2; p++) {
            int idx = tid + p * 256;
            int row = idx >> 3, cb = (idx & 7) * 16;
            cp_async16(sa + SWD(row, cb), Abase + (size_t)row * 512 + j0b + cb);
        }
#pragma unroll
        for (int p = 0; p < 8; p++) {
            int idx = tid + p * 256;
            int row = idx >> 3, cb = (idx & 7) * 16;
            cp_async16(sb + SWD(row, cb), Bbase + (size_t)row * 512 + j0b + cb);
        }
        asm volatile("cp.async.commit_group;" ::: "memory");
    };

    issue(0, 0);

    int arow = lane & 15;
    int akb = (lane >> 4) * 16;
    int brow = warp * 32 + (lane & 7) + (lane >> 4) * 8;
    int bkb = ((lane >> 3) & 1) * 16;

    for (int c = 0; c < 4; ++c) {
        int s = c & 1;
        asm volatile("cp.async.wait_group 0;" ::: "memory");
        __syncthreads();
        if (c + 1 < 4) issue(c + 1, s ^ 1);
        uint32_t sa = sbase + s * KO_STAGE;
        uint32_t sb = sa + KO_ASZ;
#pragma unroll
        for (int ks = 0; ks < 4; ks++) {
            uint32_t a[4][4];
#pragma unroll
            for (int mt = 0; mt < 4; mt++)
                ldsm_x4(a[mt], sa + SWD(arow + mt * 16, ks * 32 + akb));
            uint32_t bb[2][4];
#pragma unroll
            for (int np = 0; np < 2; np++)
                ldsm_x4(bb[np], sb + SWD(brow + np * 16, ks * 32 + bkb));
#pragma unroll
            for (int mt = 0; mt < 4; mt++)
#pragma unroll
                for (int nt = 0; nt < 4; nt++) {
                    uint32_t bfr[2] = { bb[nt >> 1][(nt & 1) * 2], bb[nt >> 1][(nt & 1) * 2 + 1] };
                    mma_bf16(acc[mt][nt], a[mt], bfr);
                }
        }
        __syncthreads();
    }

    // epilogue: residual + LN stats.  rows: mt*16 + rr*8 + r ; cols: warp*32 + nt*8 + 2cl
#pragma unroll
    for (int mt = 0; mt < 4; mt++) {
#pragma unroll
        for (int rr = 0; rr < 2; rr++) {
            int row_local = mt * 16 + rr * 8 + r;
            size_t rg = (size_t)r0 + row_local;
            const float* hrow = g_ht + rg * 256;
            float ss = 0.f, ss2 = 0.f;
#pragma unroll
            for (int nt = 0; nt < 4; nt++) {
                int col = warp * 32 + nt * 8 + 2 * cl;
                float2 hb = *(const float2*)&hrow[col];
                float2 ob = *(const float2*)&out_b[col];
                float v0 = acc[mt][nt][rr * 2 + 0] + ob.x + hb.x;
                float v1 = acc[mt][nt][rr * 2 + 1] + ob.y + hb.y;
                acc[mt][nt][rr * 2 + 0] = v0;
                acc[mt][nt][rr * 2 + 1] = v1;
                ss += v0 + v1;
                ss2 += v0 * v0 + v1 * v1;
            }
            ss += __shfl_xor_sync(0xffffffffu, ss, 1);
            ss2 += __shfl_xor_sync(0xffffffffu, ss2, 1);
            ss += __shfl_xor_sync(0xffffffffu, ss, 2);
            ss2 += __shfl_xor_sync(0xffffffffu, ss2, 2);
            if (cl == 0) {
                red[row_local * 16 + warp * 2 + 0] = ss;
                red[row_local * 16 + warp * 2 + 1] = ss2;
            }
        }
    }
    __syncthreads();
#pragma unroll
    for (int mt = 0; mt < 4; mt++) {
#pragma unroll
        for (int rr = 0; rr < 2; rr++) {
            int row_local = mt * 16 + rr * 8 + r;
            float ts = 0.f, ts2 = 0.f;
#pragma unroll
            for (int w2 = 0; w2 < 8; w2++) {
                ts += red[row_local * 16 + w2 * 2 + 0];
                ts2 += red[row_local * 16 + w2 * 2 + 1];
            }
            float mu = ts * (1.0f / 256.0f);
            float var = ts2 * (1.0f / 256.0f) - mu * mu;
            float rs = rsqrtf(var + 1e-5f);
            int rg = r0 + row_local;
            int b_ = rg >> 15, t_ = (rg >> 8) & 127, n_ = rg & 255;
            float* orow = out + (((size_t)b_ * 256 + n_) * 128 + t_) * 256;
#pragma unroll
            for (int nt = 0; nt < 4; nt++) {
                int col = warp * 32 + nt * 8 + 2 * cl;
                float2 lg = *(const float2*)&ln_g[col];
                float2 lb = *(const float2*)&ln_b[col];
                float z0 = (acc[mt][nt][rr * 2 + 0] - mu) * rs * lg.x + lb.x;
                float z1 = (acc[mt][nt][rr * 2 + 1] - mu) * rs * lg.y + lb.y;
                *(float2*)&orow[col] = make_float2(gelu_f(z0), gelu_f(z1));
            }
        }
    }
}

extern "C" void kernel_launch(void* const* d_in, const int* in_sizes, int n_in,
                              void* d_out, int out_size) {
    const float* x       = (const float*)d_in[0];
    const float* A_list  = (const float*)d_in[1];
    const float* in_w    = (const float*)d_in[2];
    const float* in_b    = (const float*)d_in[3];
    const float* out_w   = (const float*)d_in[4];
    const float* out_b   = (const float*)d_in[5];
    const float* lag     = (const float*)d_in[6];
    const float* cw1     = (const float*)d_in[7];
    const float* cb1     = (const float*)d_in[8];
    const float* cw2     = (const float*)d_in[9];
    const float* cb2     = (const float*)d_in[10];
    const float* gw1     = (const float*)d_in[11];
    const float* gb1     = (const float*)d_in[12];
    const float* gw2     = (const float*)d_in[13];
    const float* gb2     = (const float*)d_in[14];
    const float* lng     = (const float*)d_in[15];
    const float* lnb     = (const float*)d_in[16];
    float* out = (float*)d_out;

    // Idempotent host-side attribute sets (not stream ops -> graph-capture safe).
    cudaFuncSetAttribute(k_spatial_bf16, cudaFuncAttributeMaxDynamicSharedMemorySize, SP_SMEM);
    cudaFuncSetAttribute(k_out_bf16, cudaFuncAttributeMaxDynamicSharedMemorySize, KO_SMEM);

    // Order chosen so k_h2 is the 4th launch (ncu capture slot); deps respected.
    k_ctx_a<<<64, 256>>>(x);
    k_prepA<<<2048, 256>>>(A_list, lag, cw1, cb1, cw2, cb2, gw1, gb1, gw2, gb2);
    k_owT<<<dim3(8, 8), dim3(32, 8)>>>(out_w);
    k_h2<<<dim3(2, 2, 512), 256>>>(x, in_w, in_b);
    k_spatial_bf16<<<dim3(2, 2, 512), 256, SP_SMEM>>>();
    k_out_bf16<<<2048, 256, KO_SMEM>>>(out_b, lng, lnb, out);
}